// round 2
// baseline (speedup 1.0000x reference)
#include <cuda_runtime.h>
#include <math.h>

#define BB   2048
#define NNB  64
#define HH   128
#define HN   64
#define NSEQ (BB*NNB)

__device__ float g_nf[NSEQ * HN];        // neighbor GRU features
__device__ float g_tf[BB * HH];          // target GRU features
__device__ float g_enc[BB * 8 * HH];     // per-sector MLP output
__device__ float g_f1[BB * 256];         // first final-MLP layer

__device__ __forceinline__ float sigmoidf_(float x) {
    return __fdividef(1.0f, 1.0f + __expf(-x));
}
__device__ __forceinline__ float tanhf_(float x) {
    return __fdividef(2.0f, 1.0f + __expf(-2.0f * x)) - 1.0f;
}

// ============================ K1: neighbor GRU ============================
// 131072 seqs, Hn=64, gates 192. 256 threads, 4 seqs/tile, persistent.
#define K1_WT  0
#define K1_HP  (K1_WT + 64*193)
#define K1_H   (K1_HP + 4*192)
#define K1_X   (K1_H + 256)
#define K1_WIH (K1_X + 64)
#define K1_BIH (K1_WIH + 384)
#define K1_BHH (K1_BIH + 192)
#define K1_SMEM ((K1_BHH + 192) * 4)

__global__ __launch_bounds__(256)
void k1_ngru(const float* __restrict__ traj, const float* __restrict__ Wih,
             const float* __restrict__ Whh, const float* __restrict__ bih,
             const float* __restrict__ bhh)
{
    extern __shared__ float sm[];
    float *WT = sm + K1_WT, *HP = sm + K1_HP, *H = sm + K1_H, *X = sm + K1_X;
    float *WIH = sm + K1_WIH, *BIH = sm + K1_BIH, *BHH = sm + K1_BHH;
    const int tid = threadIdx.x;

    for (int idx = tid; idx < 192*64; idx += 256)
        WT[(idx & 63) * 193 + (idx >> 6)] = Whh[idx];
    for (int idx = tid; idx < 384; idx += 256) WIH[idx] = Wih[idx];
    if (tid < 192) { BIH[tid] = bih[tid]; BHH[tid] = bhh[tid]; }
    __syncthreads();

    const int s = tid >> 6, i = tid & 63;

    for (int tile = blockIdx.x; tile < NSEQ / 4; tile += gridDim.x) {
        const int seq0 = tile * 4;
        __syncthreads();
        if (tid < 64) X[tid] = traj[seq0 * 16 + tid];
        H[tid] = 0.0f;                         // H[k*4 + s]
        __syncthreads();

        #pragma unroll
        for (int t = 0; t < 8; ++t) {
            if (tid < 192) {
                float b = BHH[tid];
                float a0 = b, a1 = b, a2 = b, a3 = b;
                #pragma unroll
                for (int k = 0; k < 64; ++k) {
                    float w = WT[k * 193 + tid];
                    float4 h4 = *reinterpret_cast<const float4*>(H + k * 4);
                    a0 = fmaf(w, h4.x, a0); a1 = fmaf(w, h4.y, a1);
                    a2 = fmaf(w, h4.z, a2); a3 = fmaf(w, h4.w, a3);
                }
                HP[0*192+tid] = a0; HP[1*192+tid] = a1;
                HP[2*192+tid] = a2; HP[3*192+tid] = a3;
            }
            __syncthreads();
            {
                float x0 = X[s*16 + t*2], x1 = X[s*16 + t*2 + 1];
                float xr = fmaf(x0, WIH[2*i],       fmaf(x1, WIH[2*i+1],       BIH[i]));
                float xz = fmaf(x0, WIH[2*(64+i)],  fmaf(x1, WIH[2*(64+i)+1],  BIH[64+i]));
                float xn = fmaf(x0, WIH[2*(128+i)], fmaf(x1, WIH[2*(128+i)+1], BIH[128+i]));
                float r = sigmoidf_(xr + HP[s*192 + i]);
                float z = sigmoidf_(xz + HP[s*192 + 64 + i]);
                float n = tanhf_(xn + r * HP[s*192 + 128 + i]);
                H[i*4 + s] = (1.0f - z) * n + z * H[i*4 + s];
            }
            __syncthreads();
        }
        g_nf[seq0 * 64 + tid] = H[i*4 + s];   // tid = s*64+i -> coalesced
    }
}

// ============================ K2: target GRU ============================
// 2048 seqs, H=128, gates 384. 384 threads, 3 seqs/tile.
#define K2_WT  0
#define K2_HP  (K2_WT + 128*385)
#define K2_H   (K2_HP + 3*384)
#define K2_X   (K2_H + 384)
#define K2_WIH (K2_X + 48)
#define K2_BIH (K2_WIH + 768)
#define K2_BHH (K2_BIH + 384)
#define K2_SMEM ((K2_BHH + 384) * 4)

__global__ __launch_bounds__(384)
void k2_tgru(const float* __restrict__ traj, const float* __restrict__ Wih,
             const float* __restrict__ Whh, const float* __restrict__ bih,
             const float* __restrict__ bhh)
{
    extern __shared__ float sm[];
    float *WT = sm + K2_WT, *HP = sm + K2_HP, *H = sm + K2_H, *X = sm + K2_X;
    float *WIH = sm + K2_WIH, *BIH = sm + K2_BIH, *BHH = sm + K2_BHH;
    const int tid = threadIdx.x;

    for (int idx = tid; idx < 384*128; idx += 384)
        WT[(idx & 127) * 385 + (idx >> 7)] = Whh[idx];
    for (int idx = tid; idx < 768; idx += 384) WIH[idx] = Wih[idx];
    BIH[tid] = bih[tid]; BHH[tid] = bhh[tid];
    __syncthreads();

    const int s = tid >> 7, i = tid & 127;

    for (int tile = blockIdx.x; tile < (BB + 2) / 3; tile += gridDim.x) {
        const int seq0 = tile * 3;
        __syncthreads();
        if (tid < 48) {
            int sq = seq0 + tid / 16;
            X[tid] = (sq < BB) ? traj[sq * 16 + (tid & 15)] : 0.0f;
        }
        H[tid] = 0.0f;                        // H[s*128 + k]
        __syncthreads();

        for (int t = 0; t < 8; ++t) {
            {
                float b = BHH[tid];
                float a0 = b, a1 = b, a2 = b;
                #pragma unroll
                for (int k = 0; k < 128; k += 4) {
                    float4 h0 = *reinterpret_cast<const float4*>(H + k);
                    float4 h1 = *reinterpret_cast<const float4*>(H + 128 + k);
                    float4 h2 = *reinterpret_cast<const float4*>(H + 256 + k);
                    float w0 = WT[(k  )*385+tid], w1 = WT[(k+1)*385+tid];
                    float w2 = WT[(k+2)*385+tid], w3 = WT[(k+3)*385+tid];
                    a0 = fmaf(w0,h0.x,fmaf(w1,h0.y,fmaf(w2,h0.z,fmaf(w3,h0.w,a0))));
                    a1 = fmaf(w0,h1.x,fmaf(w1,h1.y,fmaf(w2,h1.z,fmaf(w3,h1.w,a1))));
                    a2 = fmaf(w0,h2.x,fmaf(w1,h2.y,fmaf(w2,h2.z,fmaf(w3,h2.w,a2))));
                }
                HP[tid] = a0; HP[384 + tid] = a1; HP[768 + tid] = a2;
            }
            __syncthreads();
            {
                float x0 = X[s*16 + t*2], x1 = X[s*16 + t*2 + 1];
                float xr = fmaf(x0, WIH[2*i],        fmaf(x1, WIH[2*i+1],        BIH[i]));
                float xz = fmaf(x0, WIH[2*(128+i)],  fmaf(x1, WIH[2*(128+i)+1],  BIH[128+i]));
                float xn = fmaf(x0, WIH[2*(256+i)],  fmaf(x1, WIH[2*(256+i)+1],  BIH[256+i]));
                float r = sigmoidf_(xr + HP[s*384 + i]);
                float z = sigmoidf_(xz + HP[s*384 + 128 + i]);
                float n = tanhf_(xn + r * HP[s*384 + 256 + i]);
                H[s*128 + i] = (1.0f - z) * n + z * H[s*128 + i];
            }
            __syncthreads();
        }
        int sq = seq0 + s;
        if (sq < BB) g_tf[sq * 128 + i] = H[s*128 + i];
    }
}

// =================== K3: sector features + per-sector MLP ===================
#define K3_W1T  0
#define K3_W2T  (K3_W1T + 68*129)
#define K3_NF   (K3_W2T + 128*129)
#define K3_FEAT (K3_NF + 4096)
#define K3_H1   (K3_FEAT + 8*68)
#define K3_WSUM (K3_H1 + 1024)
#define K3_WV   (K3_WSUM + 8)
#define K3_DIST (K3_WV + 64)
#define K3_VAL  (K3_DIST + 64)
#define K3_V0   (K3_VAL + 64)
#define K3_V1   (K3_V0 + 64)
#define K3_SMEM ((K3_V1 + 64) * 4)

__global__ __launch_bounds__(512)
void k3_sector(const float* __restrict__ ttraj, const float* __restrict__ ntraj,
               const float* __restrict__ ang, const float* __restrict__ mask,
               const float* __restrict__ W1, const float* __restrict__ b1,
               const float* __restrict__ W2, const float* __restrict__ b2)
{
    extern __shared__ float sm[];
    __shared__ int SID[64];
    float *W1T = sm + K3_W1T, *W2T = sm + K3_W2T, *NF = sm + K3_NF;
    float *FEAT = sm + K3_FEAT, *H1 = sm + K3_H1, *WSUM = sm + K3_WSUM;
    float *WV = sm + K3_WV, *DIST = sm + K3_DIST, *VAL = sm + K3_VAL;
    float *V0 = sm + K3_V0, *V1 = sm + K3_V1;
    const int tid = threadIdx.x;

    for (int idx = tid; idx < 128*68; idx += 512)
        W1T[(idx % 68) * 129 + (idx / 68)] = W1[idx];
    for (int idx = tid; idx < 128*128; idx += 512)
        W2T[(idx & 127) * 129 + (idx >> 7)] = W2[idx];
    __syncthreads();

    const int s = tid >> 6, i = tid & 63;

    for (int b = blockIdx.x; b < BB; b += gridDim.x) {
        __syncthreads();
        for (int idx = tid; idx < 4096; idx += 512)
            NF[idx] = g_nf[b * 4096 + idx];
        if (tid < 64) {
            const float* base = ntraj + (size_t)(b * 64 + tid) * 16;
            float px = base[14], py = base[15];
            float dx = px - ttraj[b*16 + 14], dy = py - ttraj[b*16 + 15];
            float d = sqrtf(dx*dx + dy*dy);
            DIST[tid] = d;
            V0[tid] = px - base[12];
            V1[tid] = py - base[13];
            int sid = (int)(ang[b*64 + tid] * 1.27323954473516f); // /(pi/4)
            SID[tid] = min(max(sid, 0), 7);
            float vf = (mask[b*64 + tid] > 0.0f) ? 1.0f : 0.0f;
            VAL[tid] = vf;
            WV[tid] = __expf(-d * 0.1f) * vf;
        }
        __syncthreads();
        if (tid < 8) {
            float cnt = 0.f, dsum = 0.f, v0 = 0.f, v1 = 0.f, ws = 0.f;
            for (int n = 0; n < 64; ++n) {
                bool in = (SID[n] == tid);
                float m = in ? VAL[n] : 0.0f;
                cnt += m; dsum += m * DIST[n]; v0 += m * V0[n]; v1 += m * V1[n];
                ws += in ? WV[n] : 0.0f;
            }
            float safe = fmaxf(cnt, 1.0f);
            bool ne = cnt > 0.0f;
            FEAT[tid*68 + 0] = cnt;
            FEAT[tid*68 + 1] = ne ? dsum / safe : 0.0f;
            FEAT[tid*68 + 2] = ne ? v0 / safe : 0.0f;
            FEAT[tid*68 + 3] = ne ? v1 / safe : 0.0f;
            WSUM[tid] = ws + 1e-8f;
        }
        __syncthreads();
        {
            float acc = 0.0f;
            for (int n = 0; n < 64; ++n) {
                float wm = (SID[n] == s) ? WV[n] : 0.0f;
                acc = fmaf(wm, NF[n*64 + i], acc);
            }
            FEAT[s*68 + 4 + i] = acc / WSUM[s];
        }
        __syncthreads();
        for (int o = tid; o < 1024; o += 512) {
            int os = o >> 7, oj = o & 127;
            float acc = b1[oj];
            #pragma unroll
            for (int k = 0; k < 68; ++k)
                acc = fmaf(FEAT[os*68 + k], W1T[k*129 + oj], acc);
            H1[os*128 + oj] = fmaxf(acc, 0.0f);
        }
        __syncthreads();
        for (int o = tid; o < 1024; o += 512) {
            int os = o >> 7, oj = o & 127;
            float acc = b2[oj];
            #pragma unroll
            for (int k = 0; k < 128; ++k)
                acc = fmaf(H1[os*128 + k], W2T[k*129 + oj], acc);
            g_enc[b * 1024 + o] = fmaxf(acc, 0.0f);
        }
    }
}

// =================== K5: f1 = relu([tf,enc] @ Wf1.T + bf1) ===================
// M=2048 (tile 16), N=256, K=1152 (tile 32)
__global__ __launch_bounds__(256)
void k5_f1(const float* __restrict__ Wf1, const float* __restrict__ bf1)
{
    __shared__ __align__(16) float Wsh[32 * 257];
    __shared__ __align__(16) float Ash[32 * 20];
    const int tid = threadIdx.x;
    const int m0 = blockIdx.x * 16;

    float acc[16];
    float bv = bf1[tid];
    #pragma unroll
    for (int r = 0; r < 16; ++r) acc[r] = bv;

    for (int k0 = 0; k0 < 1152; k0 += 32) {
        __syncthreads();
        for (int idx = tid; idx < 512; idx += 256) {
            int r = idx >> 5, kk = idx & 31, gk = k0 + kk;
            Ash[kk * 20 + r] = (gk < 128) ? g_tf[(m0 + r) * 128 + gk]
                                          : g_enc[(m0 + r) * 1024 + gk - 128];
        }
        {
            int jb = tid >> 5, kk = tid & 31;
            #pragma unroll
            for (int rr = 0; rr < 32; ++rr) {
                int j = jb + rr * 8;
                Wsh[kk * 257 + j] = Wf1[j * 1152 + k0 + kk];
            }
        }
        __syncthreads();
        #pragma unroll
        for (int q = 0; q < 32; ++q) {
            float w = Wsh[q * 257 + tid];
            float4 a0 = *reinterpret_cast<const float4*>(Ash + q*20);
            float4 a1 = *reinterpret_cast<const float4*>(Ash + q*20 + 4);
            float4 a2 = *reinterpret_cast<const float4*>(Ash + q*20 + 8);
            float4 a3 = *reinterpret_cast<const float4*>(Ash + q*20 + 12);
            acc[0]=fmaf(w,a0.x,acc[0]);  acc[1]=fmaf(w,a0.y,acc[1]);
            acc[2]=fmaf(w,a0.z,acc[2]);  acc[3]=fmaf(w,a0.w,acc[3]);
            acc[4]=fmaf(w,a1.x,acc[4]);  acc[5]=fmaf(w,a1.y,acc[5]);
            acc[6]=fmaf(w,a1.z,acc[6]);  acc[7]=fmaf(w,a1.w,acc[7]);
            acc[8]=fmaf(w,a2.x,acc[8]);  acc[9]=fmaf(w,a2.y,acc[9]);
            acc[10]=fmaf(w,a2.z,acc[10]); acc[11]=fmaf(w,a2.w,acc[11]);
            acc[12]=fmaf(w,a3.x,acc[12]); acc[13]=fmaf(w,a3.y,acc[13]);
            acc[14]=fmaf(w,a3.z,acc[14]); acc[15]=fmaf(w,a3.w,acc[15]);
        }
    }
    #pragma unroll
    for (int r = 0; r < 16; ++r)
        g_f1[(m0 + r) * 256 + tid] = fmaxf(acc[r], 0.0f);
}

// =================== K6: f2, f3, LayerNorm ===================
#define K6_W2T 0
#define K6_W3T (K6_W2T + 256*129)
#define K6_F1  (K6_W3T + 128*65)
#define K6_F2  (K6_F1 + 16*257)
#define K6_F3  (K6_F2 + 16*129)
#define K6_MU  (K6_F3 + 1024)
#define K6_RS  (K6_MU + 16)
#define K6_SMEM ((K6_RS + 16) * 4)

__global__ __launch_bounds__(128)
void k6_final(const float* __restrict__ Wf2, const float* __restrict__ bf2,
              const float* __restrict__ Wf3, const float* __restrict__ bf3,
              const float* __restrict__ ln_g, const float* __restrict__ ln_b,
              float* __restrict__ out)
{
    extern __shared__ float sm[];
    float *W2T = sm + K6_W2T, *W3T = sm + K6_W3T, *F1 = sm + K6_F1;
    float *F2 = sm + K6_F2, *F3 = sm + K6_F3, *MU = sm + K6_MU, *RS = sm + K6_RS;
    const int tid = threadIdx.x;
    const int m0 = blockIdx.x * 16;

    for (int idx = tid; idx < 128*256; idx += 128)
        W2T[(idx & 255) * 129 + (idx >> 8)] = Wf2[idx];
    for (int idx = tid; idx < 64*128; idx += 128)
        W3T[(idx & 127) * 65 + (idx >> 7)] = Wf3[idx];
    for (int idx = tid; idx < 16*256; idx += 128)
        F1[(idx >> 8) * 257 + (idx & 255)] = g_f1[m0 * 256 + idx];
    __syncthreads();

    {
        float acc[16];
        float bv = bf2[tid];
        #pragma unroll
        for (int r = 0; r < 16; ++r) acc[r] = bv;
        for (int k = 0; k < 256; ++k) {
            float w = W2T[k * 129 + tid];
            #pragma unroll
            for (int r = 0; r < 16; ++r)
                acc[r] = fmaf(F1[r * 257 + k], w, acc[r]);
        }
        #pragma unroll
        for (int r = 0; r < 16; ++r)
            F2[r * 129 + tid] = fmaxf(acc[r], 0.0f);
    }
    __syncthreads();
    for (int o = tid; o < 1024; o += 128) {
        int r = o >> 6, j = o & 63;
        float acc = bf3[j];
        #pragma unroll
        for (int k = 0; k < 128; ++k)
            acc = fmaf(F2[r * 129 + k], W3T[k * 65 + j], acc);
        F3[o] = fmaxf(acc, 0.0f);
    }
    __syncthreads();
    if (tid < 16) {
        float s0 = 0.f;
        #pragma unroll
        for (int j = 0; j < 64; ++j) s0 += F3[tid*64 + j];
        float mu = s0 * (1.0f / 64.0f);
        float v = 0.f;
        #pragma unroll
        for (int j = 0; j < 64; ++j) { float d = F3[tid*64 + j] - mu; v = fmaf(d, d, v); }
        MU[tid] = mu;
        RS[tid] = rsqrtf(v * (1.0f / 64.0f) + 1e-5f);
    }
    __syncthreads();
    for (int o = tid; o < 1024; o += 128) {
        int r = o >> 6, j = o & 63;
        out[(m0 + r) * 64 + j] = (F3[o] - MU[r]) * RS[r] * ln_g[j] + ln_b[j];
    }
}

// =============================== launch ===============================
extern "C" void kernel_launch(void* const* d_in, const int* in_sizes, int n_in,
                              void* d_out, int out_size)
{
    const float* ttraj = (const float*)d_in[0];
    const float* ntraj = (const float*)d_in[1];
    const float* ang   = (const float*)d_in[2];
    const float* mask  = (const float*)d_in[3];
    const float* Wih_t = (const float*)d_in[4];
    const float* Whh_t = (const float*)d_in[5];
    const float* bih_t = (const float*)d_in[6];
    const float* bhh_t = (const float*)d_in[7];
    const float* Wih_n = (const float*)d_in[8];
    const float* Whh_n = (const float*)d_in[9];
    const float* bih_n = (const float*)d_in[10];
    const float* bhh_n = (const float*)d_in[11];
    const float* W1  = (const float*)d_in[12];
    const float* b1  = (const float*)d_in[13];
    const float* W2  = (const float*)d_in[14];
    const float* b2  = (const float*)d_in[15];
    const float* Wf1 = (const float*)d_in[16];
    const float* bf1 = (const float*)d_in[17];
    const float* Wf2 = (const float*)d_in[18];
    const float* bf2 = (const float*)d_in[19];
    const float* Wf3 = (const float*)d_in[20];
    const float* bf3 = (const float*)d_in[21];
    const float* ln_g = (const float*)d_in[22];
    const float* ln_b = (const float*)d_in[23];
    float* out = (float*)d_out;

    cudaFuncSetAttribute(k1_ngru,   cudaFuncAttributeMaxDynamicSharedMemorySize, K1_SMEM);
    cudaFuncSetAttribute(k2_tgru,   cudaFuncAttributeMaxDynamicSharedMemorySize, K2_SMEM);
    cudaFuncSetAttribute(k3_sector, cudaFuncAttributeMaxDynamicSharedMemorySize, K3_SMEM);
    cudaFuncSetAttribute(k6_final,  cudaFuncAttributeMaxDynamicSharedMemorySize, K6_SMEM);

    k1_ngru<<<592, 256, K1_SMEM>>>(ntraj, Wih_n, Whh_n, bih_n, bhh_n);
    k2_tgru<<<148, 384, K2_SMEM>>>(ttraj, Wih_t, Whh_t, bih_t, bhh_t);
    k3_sector<<<148, 512, K3_SMEM>>>(ttraj, ntraj, ang, mask, W1, b1, W2, b2);
    k5_f1<<<128, 256>>>(Wf1, bf1);
    k6_final<<<128, 128, K6_SMEM>>>(Wf2, bf2, Wf3, bf3, ln_g, ln_b, out);
}

// round 6
// speedup vs baseline: 1.3012x; 1.3012x over previous
#include <cuda_runtime.h>
#include <math.h>

#define BB   2048
#define NNB  64
#define HH   128
#define HN   64
#define NSEQ (BB*NNB)

typedef unsigned long long u64;

__device__ float g_nf[NSEQ * HN];        // neighbor GRU features
__device__ float g_tf[BB * HH];          // target GRU features
__device__ float g_enc[BB * 8 * HH];     // per-sector MLP output
__device__ float g_f1[BB * 256];         // first final-MLP layer

__device__ __forceinline__ float sigmoidf_(float x) {
    return __fdividef(1.0f, 1.0f + __expf(-x));
}
__device__ __forceinline__ float tanhf_(float x) {
    return __fdividef(2.0f, 1.0f + __expf(-2.0f * x)) - 1.0f;
}

// packed f32x2 helpers (u64 carrier)
__device__ __forceinline__ u64 ffma2(u64 a, u64 b, u64 c) {
    u64 d;
    asm("fma.rn.f32x2 %0, %1, %2, %3;" : "=l"(d) : "l"(a), "l"(b), "l"(c));
    return d;
}
__device__ __forceinline__ float2 unpk(u64 a) {
    float2 r; asm("mov.b64 {%0, %1}, %2;" : "=f"(r.x), "=f"(r.y) : "l"(a));
    return r;
}
__device__ __forceinline__ u64 pk(float lo, float hi) {
    u64 d; asm("mov.b64 %0, {%1, %2};" : "=l"(d) : "f"(lo), "f"(hi));
    return d;
}

// ============================ K1: neighbor GRU ============================
// 131072 seqs, 1 seq/thread, h packed f32x2 in registers, zero block syncs
// in the time loop. grid 256 x 512 threads = 131072 threads exactly.
#define K1_SMEM (49152 + 1536 + 131072 + 32768 + 1536)

__global__ __launch_bounds__(512)
void k1_ngru(const float* __restrict__ traj, const float* __restrict__ Wih,
             const float* __restrict__ Whh, const float* __restrict__ bih,
             const float* __restrict__ bhh)
{
    extern __shared__ u64 smd[];
    u64*   WS   = smd;                    // 6144 u64: Whh natural (k,k+1) pairs
    u64*   WIHd = WS + 6144;              // 192 u64
    float* HS   = (float*)(WIHd + 192);   // 64*512 scalar h, thread-major
    float* XS   = HS + 64*512;            // 16*512
    float* BIH  = XS + 16*512;            // 192
    float* BHH  = BIH + 192;              // 192

    const int tid = threadIdx.x;
    const int seq = blockIdx.x * 512 + tid;

    const u64* Wg = (const u64*)Whh;
    for (int idx = tid; idx < 6144; idx += 512) WS[idx] = Wg[idx];
    const u64* WIHg = (const u64*)Wih;
    if (tid < 192) {
        WIHd[tid] = WIHg[tid];
        BIH[tid] = bih[tid];
        BHH[tid] = bhh[tid];
    }

    // per-thread x staging (own column, no sync needed)
    {
        const float4* tp = (const float4*)(traj + (size_t)seq * 16);
        float4 a = tp[0], b = tp[1], c = tp[2], d = tp[3];
        XS[ 0*512+tid]=a.x; XS[ 1*512+tid]=a.y; XS[ 2*512+tid]=a.z; XS[ 3*512+tid]=a.w;
        XS[ 4*512+tid]=b.x; XS[ 5*512+tid]=b.y; XS[ 6*512+tid]=b.z; XS[ 7*512+tid]=b.w;
        XS[ 8*512+tid]=c.x; XS[ 9*512+tid]=c.y; XS[10*512+tid]=c.z; XS[11*512+tid]=c.w;
        XS[12*512+tid]=d.x; XS[13*512+tid]=d.y; XS[14*512+tid]=d.z; XS[15*512+tid]=d.w;
    }

    u64 h[32];
    const u64 zero2 = 0ull;
    #pragma unroll
    for (int p = 0; p < 32; ++p) h[p] = zero2;
    #pragma unroll
    for (int i = 0; i < 64; ++i) HS[i*512 + tid] = 0.0f;

    __syncthreads();   // weights visible; only sync in the kernel

    for (int t = 0; t < 8; ++t) {
        float x0 = XS[(2*t)*512 + tid];
        float x1 = XS[(2*t+1)*512 + tid];
        u64 x2 = pk(x0, x1);

        for (int i = 0; i < 64; ++i) {
            const ulonglong2* wr = (const ulonglong2*)(WS + (size_t)i*32);
            const ulonglong2* wz = (const ulonglong2*)(WS + (size_t)(64+i)*32);
            const ulonglong2* wn = (const ulonglong2*)(WS + (size_t)(128+i)*32);
            u64 ar = zero2, az = zero2, an = zero2;
            #pragma unroll
            for (int p = 0; p < 16; ++p) {
                ulonglong2 a = wr[p], b = wz[p], c = wn[p];
                ar = ffma2(a.x, h[2*p],   ar);
                az = ffma2(b.x, h[2*p],   az);
                an = ffma2(c.x, h[2*p],   an);
                ar = ffma2(a.y, h[2*p+1], ar);
                az = ffma2(b.y, h[2*p+1], az);
                an = ffma2(c.y, h[2*p+1], an);
            }
            u64 xr2 = ffma2(WIHd[i],     x2, zero2);
            u64 xz2 = ffma2(WIHd[64+i],  x2, zero2);
            u64 xn2 = ffma2(WIHd[128+i], x2, zero2);
            float2 u;
            u = unpk(ar);  float hr = u.x + u.y + BHH[i];
            u = unpk(az);  float hz = u.x + u.y + BHH[64+i];
            u = unpk(an);  float hn = u.x + u.y + BHH[128+i];
            u = unpk(xr2); float xr = u.x + u.y + BIH[i];
            u = unpk(xz2); float xz = u.x + u.y + BIH[64+i];
            u = unpk(xn2); float xn = u.x + u.y + BIH[128+i];
            float r = sigmoidf_(xr + hr);
            float z = sigmoidf_(xz + hz);
            float n = tanhf_(xn + r * hn);
            float hold = HS[i*512 + tid];
            HS[i*512 + tid] = (1.0f - z) * n + z * hold;
        }
        // reload packed h from scalar copy (own column, no sync)
        #pragma unroll
        for (int p = 0; p < 32; ++p)
            h[p] = pk(HS[(2*p)*512 + tid], HS[(2*p+1)*512 + tid]);
    }

    float* dst = g_nf + (size_t)seq * 64;
    #pragma unroll
    for (int q = 0; q < 16; ++q) {
        float4 v = make_float4(HS[(4*q+0)*512 + tid], HS[(4*q+1)*512 + tid],
                               HS[(4*q+2)*512 + tid], HS[(4*q+3)*512 + tid]);
        ((float4*)dst)[q] = v;
    }
}

// ============================ K2: target GRU ============================
#define K2_WT  0
#define K2_HP  (K2_WT + 128*385)
#define K2_H   (K2_HP + 3*384)
#define K2_X   (K2_H + 384)
#define K2_WIH (K2_X + 48)
#define K2_BIH (K2_WIH + 768)
#define K2_BHH (K2_BIH + 384)
#define K2_SMEM ((K2_BHH + 384) * 4)

__global__ __launch_bounds__(384)
void k2_tgru(const float* __restrict__ traj, const float* __restrict__ Wih,
             const float* __restrict__ Whh, const float* __restrict__ bih,
             const float* __restrict__ bhh)
{
    extern __shared__ float sm[];
    float *WT = sm + K2_WT, *HP = sm + K2_HP, *H = sm + K2_H, *X = sm + K2_X;
    float *WIH = sm + K2_WIH, *BIH = sm + K2_BIH, *BHH = sm + K2_BHH;
    const int tid = threadIdx.x;

    for (int idx = tid; idx < 384*128; idx += 384)
        WT[(idx & 127) * 385 + (idx >> 7)] = Whh[idx];
    for (int idx = tid; idx < 768; idx += 384) WIH[idx] = Wih[idx];
    BIH[tid] = bih[tid]; BHH[tid] = bhh[tid];
    __syncthreads();

    const int s = tid >> 7, i = tid & 127;

    for (int tile = blockIdx.x; tile < (BB + 2) / 3; tile += gridDim.x) {
        const int seq0 = tile * 3;
        __syncthreads();
        if (tid < 48) {
            int sq = seq0 + tid / 16;
            X[tid] = (sq < BB) ? traj[sq * 16 + (tid & 15)] : 0.0f;
        }
        H[tid] = 0.0f;
        __syncthreads();

        for (int t = 0; t < 8; ++t) {
            {
                float b = BHH[tid];
                float a0 = b, a1 = b, a2 = b;
                #pragma unroll
                for (int k = 0; k < 128; k += 4) {
                    float4 h0 = *reinterpret_cast<const float4*>(H + k);
                    float4 h1 = *reinterpret_cast<const float4*>(H + 128 + k);
                    float4 h2 = *reinterpret_cast<const float4*>(H + 256 + k);
                    float w0 = WT[(k  )*385+tid], w1 = WT[(k+1)*385+tid];
                    float w2 = WT[(k+2)*385+tid], w3 = WT[(k+3)*385+tid];
                    a0 = fmaf(w0,h0.x,fmaf(w1,h0.y,fmaf(w2,h0.z,fmaf(w3,h0.w,a0))));
                    a1 = fmaf(w0,h1.x,fmaf(w1,h1.y,fmaf(w2,h1.z,fmaf(w3,h1.w,a1))));
                    a2 = fmaf(w0,h2.x,fmaf(w1,h2.y,fmaf(w2,h2.z,fmaf(w3,h2.w,a2))));
                }
                HP[tid] = a0; HP[384 + tid] = a1; HP[768 + tid] = a2;
            }
            __syncthreads();
            {
                float x0 = X[s*16 + t*2], x1 = X[s*16 + t*2 + 1];
                float xr = fmaf(x0, WIH[2*i],        fmaf(x1, WIH[2*i+1],        BIH[i]));
                float xz = fmaf(x0, WIH[2*(128+i)],  fmaf(x1, WIH[2*(128+i)+1],  BIH[128+i]));
                float xn = fmaf(x0, WIH[2*(256+i)],  fmaf(x1, WIH[2*(256+i)+1],  BIH[256+i]));
                float r = sigmoidf_(xr + HP[s*384 + i]);
                float z = sigmoidf_(xz + HP[s*384 + 128 + i]);
                float n = tanhf_(xn + r * HP[s*384 + 256 + i]);
                H[s*128 + i] = (1.0f - z) * n + z * H[s*128 + i];
            }
            __syncthreads();
        }
        int sq = seq0 + s;
        if (sq < BB) g_tf[sq * 128 + i] = H[s*128 + i];
    }
}

// =================== K3: sector features + per-sector MLP ===================
#define K3_W1T  0
#define K3_W2T  (K3_W1T + 68*129)
#define K3_NF   (K3_W2T + 128*129)
#define K3_FEAT (K3_NF + 4096)
#define K3_H1   (K3_FEAT + 8*68)
#define K3_WSUM (K3_H1 + 1024)
#define K3_WV   (K3_WSUM + 8)
#define K3_DIST (K3_WV + 64)
#define K3_VAL  (K3_DIST + 64)
#define K3_V0   (K3_VAL + 64)
#define K3_V1   (K3_V0 + 64)
#define K3_SMEM ((K3_V1 + 64) * 4)

__global__ __launch_bounds__(512)
void k3_sector(const float* __restrict__ ttraj, const float* __restrict__ ntraj,
               const float* __restrict__ ang, const float* __restrict__ mask,
               const float* __restrict__ W1, const float* __restrict__ b1,
               const float* __restrict__ W2, const float* __restrict__ b2)
{
    extern __shared__ float smf[];
    __shared__ int SID[64];
    float *W1T = smf + K3_W1T, *W2T = smf + K3_W2T, *NF = smf + K3_NF;
    float *FEAT = smf + K3_FEAT, *H1 = smf + K3_H1, *WSUM = smf + K3_WSUM;
    float *WV = smf + K3_WV, *DIST = smf + K3_DIST, *VAL = smf + K3_VAL;
    float *V0 = smf + K3_V0, *V1 = smf + K3_V1;
    const int tid = threadIdx.x;

    for (int idx = tid; idx < 128*68; idx += 512)
        W1T[(idx % 68) * 129 + (idx / 68)] = W1[idx];
    for (int idx = tid; idx < 128*128; idx += 512)
        W2T[(idx & 127) * 129 + (idx >> 7)] = W2[idx];
    __syncthreads();

    const int s = tid >> 6, i = tid & 63;

    for (int b = blockIdx.x; b < BB; b += gridDim.x) {
        __syncthreads();
        for (int idx = tid; idx < 4096; idx += 512)
            NF[idx] = g_nf[b * 4096 + idx];
        if (tid < 64) {
            const float* base = ntraj + (size_t)(b * 64 + tid) * 16;
            float px = base[14], py = base[15];
            float dx = px - ttraj[b*16 + 14], dy = py - ttraj[b*16 + 15];
            float d = sqrtf(dx*dx + dy*dy);
            DIST[tid] = d;
            V0[tid] = px - base[12];
            V1[tid] = py - base[13];
            int sid = (int)(ang[b*64 + tid] * 1.27323954473516f);
            SID[tid] = min(max(sid, 0), 7);
            float vf = (mask[b*64 + tid] > 0.0f) ? 1.0f : 0.0f;
            VAL[tid] = vf;
            WV[tid] = __expf(-d * 0.1f) * vf;
        }
        __syncthreads();
        if (tid < 8) {
            float cnt = 0.f, dsum = 0.f, v0 = 0.f, v1 = 0.f, ws = 0.f;
            for (int n = 0; n < 64; ++n) {
                bool in = (SID[n] == tid);
                float m = in ? VAL[n] : 0.0f;
                cnt += m; dsum += m * DIST[n]; v0 += m * V0[n]; v1 += m * V1[n];
                ws += in ? WV[n] : 0.0f;
            }
            float safe = fmaxf(cnt, 1.0f);
            bool ne = cnt > 0.0f;
            FEAT[tid*68 + 0] = cnt;
            FEAT[tid*68 + 1] = ne ? dsum / safe : 0.0f;
            FEAT[tid*68 + 2] = ne ? v0 / safe : 0.0f;
            FEAT[tid*68 + 3] = ne ? v1 / safe : 0.0f;
            WSUM[tid] = ws + 1e-8f;
        }
        __syncthreads();
        {
            float acc = 0.0f;
            for (int n = 0; n < 64; ++n) {
                float wm = (SID[n] == s) ? WV[n] : 0.0f;
                acc = fmaf(wm, NF[n*64 + i], acc);
            }
            FEAT[s*68 + 4 + i] = acc / WSUM[s];
        }
        __syncthreads();
        for (int o = tid; o < 1024; o += 512) {
            int os = o >> 7, oj = o & 127;
            float acc = b1[oj];
            #pragma unroll
            for (int k = 0; k < 68; ++k)
                acc = fmaf(FEAT[os*68 + k], W1T[k*129 + oj], acc);
            H1[os*128 + oj] = fmaxf(acc, 0.0f);
        }
        __syncthreads();
        for (int o = tid; o < 1024; o += 512) {
            int os = o >> 7, oj = o & 127;
            float acc = b2[oj];
            #pragma unroll
            for (int k = 0; k < 128; ++k)
                acc = fmaf(H1[os*128 + k], W2T[k*129 + oj], acc);
            g_enc[b * 1024 + o] = fmaxf(acc, 0.0f);
        }
    }
}

// =================== K5: f1 = relu([tf,enc] @ Wf1.T + bf1) ===================
// M=2048 (tile 8), N=256, K=1152 (chunk 32), double-buffered (dynamic smem).
#define K5_PAD 12
#define K5_SMEM ((2*32*257 + 2*32*K5_PAD) * 4)

__global__ __launch_bounds__(256)
void k5_f1(const float* __restrict__ Wf1, const float* __restrict__ bf1)
{
    extern __shared__ float k5s[];
    float* Wsh0 = k5s;                    // [2][32*257]
    float* Ash0 = k5s + 2*32*257;         // [2][32*K5_PAD]

    const int tid = threadIdx.x;
    const int m0 = blockIdx.x * 8;
    const int jb = tid >> 5, kk = tid & 31;

    float acc[8];
    float bv = bf1[tid];
    #pragma unroll
    for (int r = 0; r < 8; ++r) acc[r] = bv;

    float wreg[32];
    float areg;

    // prefetch chunk 0 (k0 = 0, so A source is g_tf)
    #pragma unroll
    for (int rr = 0; rr < 32; ++rr)
        wreg[rr] = Wf1[(jb + rr * 8) * 1152 + kk];
    areg = g_tf[(m0 + jb) * 128 + kk];

    for (int c = 0; c < 36; ++c) {
        float* Wsh = Wsh0 + (c & 1) * (32 * 257);
        float* Ash = Ash0 + (c & 1) * (32 * K5_PAD);
        __syncthreads();
        #pragma unroll
        for (int rr = 0; rr < 32; ++rr)
            Wsh[kk * 257 + jb + rr * 8] = wreg[rr];
        Ash[kk * K5_PAD + jb] = areg;
        __syncthreads();
        if (c < 35) {
            const int k0 = (c + 1) * 32;
            #pragma unroll
            for (int rr = 0; rr < 32; ++rr)
                wreg[rr] = Wf1[(jb + rr * 8) * 1152 + k0 + kk];
            int gk = k0 + kk;
            areg = (gk < 128) ? g_tf[(m0 + jb) * 128 + gk]
                              : g_enc[(m0 + jb) * 1024 + gk - 128];
        }
        #pragma unroll
        for (int q = 0; q < 32; ++q) {
            float w = Wsh[q * 257 + tid];
            float4 a0 = *reinterpret_cast<const float4*>(&Ash[q * K5_PAD]);
            float4 a1 = *reinterpret_cast<const float4*>(&Ash[q * K5_PAD + 4]);
            acc[0]=fmaf(w,a0.x,acc[0]); acc[1]=fmaf(w,a0.y,acc[1]);
            acc[2]=fmaf(w,a0.z,acc[2]); acc[3]=fmaf(w,a0.w,acc[3]);
            acc[4]=fmaf(w,a1.x,acc[4]); acc[5]=fmaf(w,a1.y,acc[5]);
            acc[6]=fmaf(w,a1.z,acc[6]); acc[7]=fmaf(w,a1.w,acc[7]);
        }
    }
    #pragma unroll
    for (int r = 0; r < 8; ++r)
        g_f1[(m0 + r) * 256 + tid] = fmaxf(acc[r], 0.0f);
}

// =================== K6: f2, f3, LayerNorm ===================
#define K6_W2T 0
#define K6_W3T (K6_W2T + 256*129)
#define K6_F1  (K6_W3T + 128*65)
#define K6_F2  (K6_F1 + 16*257)
#define K6_F3  (K6_F2 + 16*129)
#define K6_MU  (K6_F3 + 1024)
#define K6_RS  (K6_MU + 16)
#define K6_SMEM ((K6_RS + 16) * 4)

__global__ __launch_bounds__(128)
void k6_final(const float* __restrict__ Wf2, const float* __restrict__ bf2,
              const float* __restrict__ Wf3, const float* __restrict__ bf3,
              const float* __restrict__ ln_g, const float* __restrict__ ln_b,
              float* __restrict__ out)
{
    extern __shared__ float smf[];
    float *W2T = smf + K6_W2T, *W3T = smf + K6_W3T, *F1 = smf + K6_F1;
    float *F2 = smf + K6_F2, *F3 = smf + K6_F3, *MU = smf + K6_MU, *RS = smf + K6_RS;
    const int tid = threadIdx.x;
    const int m0 = blockIdx.x * 16;

    for (int idx = tid; idx < 128*256; idx += 128)
        W2T[(idx & 255) * 129 + (idx >> 8)] = Wf2[idx];
    for (int idx = tid; idx < 64*128; idx += 128)
        W3T[(idx & 127) * 65 + (idx >> 7)] = Wf3[idx];
    for (int idx = tid; idx < 16*256; idx += 128)
        F1[(idx >> 8) * 257 + (idx & 255)] = g_f1[m0 * 256 + idx];
    __syncthreads();

    {
        float acc[16];
        float bv = bf2[tid];
        #pragma unroll
        for (int r = 0; r < 16; ++r) acc[r] = bv;
        for (int k = 0; k < 256; ++k) {
            float w = W2T[k * 129 + tid];
            #pragma unroll
            for (int r = 0; r < 16; ++r)
                acc[r] = fmaf(F1[r * 257 + k], w, acc[r]);
        }
        #pragma unroll
        for (int r = 0; r < 16; ++r)
            F2[r * 129 + tid] = fmaxf(acc[r], 0.0f);
    }
    __syncthreads();
    for (int o = tid; o < 1024; o += 128) {
        int r = o >> 6, j = o & 63;
        float acc = bf3[j];
        #pragma unroll
        for (int k = 0; k < 128; ++k)
            acc = fmaf(F2[r * 129 + k], W3T[k * 65 + j], acc);
        F3[o] = fmaxf(acc, 0.0f);
    }
    __syncthreads();
    if (tid < 16) {
        float s0 = 0.f;
        #pragma unroll
        for (int j = 0; j < 64; ++j) s0 += F3[tid*64 + j];
        float mu = s0 * (1.0f / 64.0f);
        float v = 0.f;
        #pragma unroll
        for (int j = 0; j < 64; ++j) { float d = F3[tid*64 + j] - mu; v = fmaf(d, d, v); }
        MU[tid] = mu;
        RS[tid] = rsqrtf(v * (1.0f / 64.0f) + 1e-5f);
    }
    __syncthreads();
    for (int o = tid; o < 1024; o += 128) {
        int r = o >> 6, j = o & 63;
        out[(m0 + r) * 64 + j] = (F3[o] - MU[r]) * RS[r] * ln_g[j] + ln_b[j];
    }
}

// =============================== launch ===============================
extern "C" void kernel_launch(void* const* d_in, const int* in_sizes, int n_in,
                              void* d_out, int out_size)
{
    const float* ttraj = (const float*)d_in[0];
    const float* ntraj = (const float*)d_in[1];
    const float* ang   = (const float*)d_in[2];
    const float* mask  = (const float*)d_in[3];
    const float* Wih_t = (const float*)d_in[4];
    const float* Whh_t = (const float*)d_in[5];
    const float* bih_t = (const float*)d_in[6];
    const float* bhh_t = (const float*)d_in[7];
    const float* Wih_n = (const float*)d_in[8];
    const float* Whh_n = (const float*)d_in[9];
    const float* bih_n = (const float*)d_in[10];
    const float* bhh_n = (const float*)d_in[11];
    const float* W1  = (const float*)d_in[12];
    const float* b1  = (const float*)d_in[13];
    const float* W2  = (const float*)d_in[14];
    const float* b2  = (const float*)d_in[15];
    const float* Wf1 = (const float*)d_in[16];
    const float* bf1 = (const float*)d_in[17];
    const float* Wf2 = (const float*)d_in[18];
    const float* bf2 = (const float*)d_in[19];
    const float* Wf3 = (const float*)d_in[20];
    const float* bf3 = (const float*)d_in[21];
    const float* ln_g = (const float*)d_in[22];
    const float* ln_b = (const float*)d_in[23];
    float* out = (float*)d_out;

    cudaFuncSetAttribute(k1_ngru,   cudaFuncAttributeMaxDynamicSharedMemorySize, K1_SMEM);
    cudaFuncSetAttribute(k2_tgru,   cudaFuncAttributeMaxDynamicSharedMemorySize, K2_SMEM);
    cudaFuncSetAttribute(k3_sector, cudaFuncAttributeMaxDynamicSharedMemorySize, K3_SMEM);
    cudaFuncSetAttribute(k5_f1,     cudaFuncAttributeMaxDynamicSharedMemorySize, K5_SMEM);
    cudaFuncSetAttribute(k6_final,  cudaFuncAttributeMaxDynamicSharedMemorySize, K6_SMEM);

    k1_ngru<<<256, 512, K1_SMEM>>>(ntraj, Wih_n, Whh_n, bih_n, bhh_n);
    k2_tgru<<<148, 384, K2_SMEM>>>(ttraj, Wih_t, Whh_t, bih_t, bhh_t);
    k3_sector<<<296, 512, K3_SMEM>>>(ttraj, ntraj, ang, mask, W1, b1, W2, b2);
    k5_f1<<<256, 256, K5_SMEM>>>(Wf1, bf1);
    k6_final<<<128, 128, K6_SMEM>>>(Wf2, bf2, Wf3, bf3, ln_g, ln_b, out);
}

// round 10
// speedup vs baseline: 1.6956x; 1.3032x over previous
#include <cuda_runtime.h>
#include <stdint.h>
#include <math.h>

#define BB   2048
#define NNB  64
#define HH   128
#define HN   64
#define NSEQ (BB*NNB)

typedef unsigned long long u64;

__device__ float g_nf[NSEQ * HN];        // neighbor GRU features
__device__ float g_tf[BB * HH];          // target GRU features
__device__ float g_enc[BB * 8 * HH];     // per-sector MLP output
__device__ float g_f1[BB * 256];         // first final-MLP layer

__device__ __forceinline__ float sigmoidf_(float x) {
    return __fdividef(1.0f, 1.0f + __expf(-x));
}
__device__ __forceinline__ float tanhf_(float x) {
    return __fdividef(2.0f, 1.0f + __expf(-2.0f * x)) - 1.0f;
}

// packed f32x2 helpers (u64 carrier)
__device__ __forceinline__ u64 ffma2(u64 a, u64 b, u64 c) {
    u64 d;
    asm("fma.rn.f32x2 %0, %1, %2, %3;" : "=l"(d) : "l"(a), "l"(b), "l"(c));
    return d;
}
__device__ __forceinline__ float2 unpk(u64 a) {
    float2 r; asm("mov.b64 {%0, %1}, %2;" : "=f"(r.x), "=f"(r.y) : "l"(a));
    return r;
}
__device__ __forceinline__ u64 pk(float lo, float hi) {
    u64 d; asm("mov.b64 %0, {%1, %2};" : "=l"(d) : "f"(lo), "f"(hi));
    return d;
}

// ===================== K1: neighbor GRU, register-blocked f32x2 =====================
// 256 threads = 16 j-groups x 16 seq-groups; tile = 64 seqs; thread tile 4 seqs x 12 j.
// Thread's j-set = {i0..i0+3} U {64+i0..} U {128+i0..} so gates are computed locally.
// Weights pre-paired in shared (u64), h double-buffered in shared, 1 sync/step.
#define G1_S      64
#define G1_WT2_B  0                 // u64 [64][96]   49152 B
#define G1_HSA_B  49152             // float [64][64] 16384 B
#define G1_HSB_B  65536             // float [64][64] 16384 B
#define G1_XS_B   81920             // float [16][64]  4096 B
#define G1_WIH_B  86016             // float2 [192]    1536 B
#define G1_BIH_B  87552             // float [192]      768 B
#define G1_BHH_B  88320             // float [192]      768 B
#define G1_BHH2_B 89088             // u64 [96]         768 B
#define G1_SMEM   89856

__global__ __launch_bounds__(256, 2)
void k1_ngru(const float* __restrict__ traj, const float* __restrict__ Wih,
             const float* __restrict__ Whh, const float* __restrict__ bih,
             const float* __restrict__ bhh)
{
    extern __shared__ char sm1[];
    u64*    WT2  = (u64*)(sm1 + G1_WT2_B);
    float*  XS   = (float*)(sm1 + G1_XS_B);
    float2* WIH2 = (float2*)(sm1 + G1_WIH_B);
    float*  BIH  = (float*)(sm1 + G1_BIH_B);
    float*  BHH  = (float*)(sm1 + G1_BHH_B);
    u64*    BHH2 = (u64*)(sm1 + G1_BHH2_B);

    const int tid = threadIdx.x;
    const int tj = tid & 15, ts = tid >> 4;
    const int i0 = tj * 4, s0 = ts * 4;

    // stage weights once (persist across tiles)
    for (int idx = tid; idx < 96 * 64; idx += 256) {
        int jp = idx >> 6, k = idx & 63;
        WT2[k * 96 + jp] = pk(Whh[(2 * jp) * 64 + k], Whh[(2 * jp + 1) * 64 + k]);
    }
    if (tid < 192) {
        WIH2[tid] = ((const float2*)Wih)[tid];
        BIH[tid] = bih[tid];
        BHH[tid] = bhh[tid];
    }
    if (tid < 96) BHH2[tid] = pk(bhh[2 * tid], bhh[2 * tid + 1]);
    __syncthreads();

    for (int tile = blockIdx.x; tile < NSEQ / G1_S; tile += gridDim.x) {
        const int seqbase = tile * G1_S;
        {   // stage X: 64 seqs x 16 floats, transposed to XS[comp][s]
            int s = tid >> 2, q = tid & 3;
            float4 v = ((const float4*)(traj + (size_t)(seqbase + s) * 16))[q];
            XS[(4 * q + 0) * 64 + s] = v.x;
            XS[(4 * q + 1) * 64 + s] = v.y;
            XS[(4 * q + 2) * 64 + s] = v.z;
            XS[(4 * q + 3) * 64 + s] = v.w;
        }
        __syncthreads();

        for (int t = 0; t < 8; ++t) {
            float* HSr = (float*)(sm1 + ((t & 1) ? G1_HSB_B : G1_HSA_B));
            float* HSw = (float*)(sm1 + ((t & 1) ? G1_HSA_B : G1_HSB_B));
            u64 acc[4][6];

            if (t > 0) {
                #pragma unroll
                for (int s = 0; s < 4; ++s) {
                    acc[s][0] = BHH2[2 * tj];      acc[s][1] = BHH2[2 * tj + 1];
                    acc[s][2] = BHH2[32 + 2 * tj]; acc[s][3] = BHH2[33 + 2 * tj];
                    acc[s][4] = BHH2[64 + 2 * tj]; acc[s][5] = BHH2[65 + 2 * tj];
                }
                #pragma unroll 4
                for (int k = 0; k < 64; ++k) {
                    ulonglong2 wr = *(const ulonglong2*)&WT2[k * 96 + 2 * tj];
                    ulonglong2 wz = *(const ulonglong2*)&WT2[k * 96 + 32 + 2 * tj];
                    ulonglong2 wn = *(const ulonglong2*)&WT2[k * 96 + 64 + 2 * tj];
                    float4 hv = *(const float4*)&HSr[k * 64 + s0];
                    u64 h0 = pk(hv.x, hv.x), h1 = pk(hv.y, hv.y);
                    u64 h2 = pk(hv.z, hv.z), h3 = pk(hv.w, hv.w);
                    acc[0][0]=ffma2(wr.x,h0,acc[0][0]); acc[0][1]=ffma2(wr.y,h0,acc[0][1]);
                    acc[0][2]=ffma2(wz.x,h0,acc[0][2]); acc[0][3]=ffma2(wz.y,h0,acc[0][3]);
                    acc[0][4]=ffma2(wn.x,h0,acc[0][4]); acc[0][5]=ffma2(wn.y,h0,acc[0][5]);
                    acc[1][0]=ffma2(wr.x,h1,acc[1][0]); acc[1][1]=ffma2(wr.y,h1,acc[1][1]);
                    acc[1][2]=ffma2(wz.x,h1,acc[1][2]); acc[1][3]=ffma2(wz.y,h1,acc[1][3]);
                    acc[1][4]=ffma2(wn.x,h1,acc[1][4]); acc[1][5]=ffma2(wn.y,h1,acc[1][5]);
                    acc[2][0]=ffma2(wr.x,h2,acc[2][0]); acc[2][1]=ffma2(wr.y,h2,acc[2][1]);
                    acc[2][2]=ffma2(wz.x,h2,acc[2][2]); acc[2][3]=ffma2(wz.y,h2,acc[2][3]);
                    acc[2][4]=ffma2(wn.x,h2,acc[2][4]); acc[2][5]=ffma2(wn.y,h2,acc[2][5]);
                    acc[3][0]=ffma2(wr.x,h3,acc[3][0]); acc[3][1]=ffma2(wr.y,h3,acc[3][1]);
                    acc[3][2]=ffma2(wz.x,h3,acc[3][2]); acc[3][3]=ffma2(wz.y,h3,acc[3][3]);
                    acc[3][4]=ffma2(wn.x,h3,acc[3][4]); acc[3][5]=ffma2(wn.y,h3,acc[3][5]);
                }
            }

            // gates (thread-local: its own j-set covers r/z/n for i0..i0+3)
            #pragma unroll
            for (int s = 0; s < 4; ++s) {
                int ss = s0 + s;
                float x0 = XS[(2 * t) * 64 + ss];
                float x1 = XS[(2 * t + 1) * 64 + ss];
                #pragma unroll
                for (int pp = 0; pp < 2; ++pp) {
                    float2 ar, az, an;
                    if (t > 0) {
                        ar = unpk(acc[s][pp]); az = unpk(acc[s][2 + pp]); an = unpk(acc[s][4 + pp]);
                    } else {
                        int ib = i0 + 2 * pp;
                        ar = make_float2(BHH[ib], BHH[ib + 1]);
                        az = make_float2(BHH[64 + ib], BHH[65 + ib]);
                        an = make_float2(BHH[128 + ib], BHH[129 + ib]);
                    }
                    #pragma unroll
                    for (int c = 0; c < 2; ++c) {
                        int i = i0 + 2 * pp + c;
                        float hrv = c ? ar.y : ar.x;
                        float hzv = c ? az.y : az.x;
                        float hnv = c ? an.y : an.x;
                        float2 wr2 = WIH2[i], wz2 = WIH2[64 + i], wn2 = WIH2[128 + i];
                        float xr = fmaf(x0, wr2.x, fmaf(x1, wr2.y, BIH[i]));
                        float xz = fmaf(x0, wz2.x, fmaf(x1, wz2.y, BIH[64 + i]));
                        float xn = fmaf(x0, wn2.x, fmaf(x1, wn2.y, BIH[128 + i]));
                        float r = sigmoidf_(xr + hrv);
                        float z = sigmoidf_(xz + hzv);
                        float n = tanhf_(xn + r * hnv);
                        float hold = (t > 0) ? HSr[i * 64 + ss] : 0.0f;
                        float h = (1.0f - z) * n + z * hold;
                        if (t < 7) HSw[i * 64 + ss] = h;
                        else       g_nf[(size_t)(seqbase + ss) * 64 + i] = h;
                    }
                }
            }
            __syncthreads();
        }
    }
}

// ============================ K2: target GRU ============================
#define K2_WT  0
#define K2_HP  (K2_WT + 128*385)
#define K2_H   (K2_HP + 3*384)
#define K2_X   (K2_H + 384)
#define K2_WIH (K2_X + 48)
#define K2_BIH (K2_WIH + 768)
#define K2_BHH (K2_BIH + 384)
#define K2_SMEM ((K2_BHH + 384) * 4)

__global__ __launch_bounds__(384)
void k2_tgru(const float* __restrict__ traj, const float* __restrict__ Wih,
             const float* __restrict__ Whh, const float* __restrict__ bih,
             const float* __restrict__ bhh)
{
    extern __shared__ float sm[];
    float *WT = sm + K2_WT, *HP = sm + K2_HP, *H = sm + K2_H, *X = sm + K2_X;
    float *WIH = sm + K2_WIH, *BIH = sm + K2_BIH, *BHH = sm + K2_BHH;
    const int tid = threadIdx.x;

    for (int idx = tid; idx < 384*128; idx += 384)
        WT[(idx & 127) * 385 + (idx >> 7)] = Whh[idx];
    for (int idx = tid; idx < 768; idx += 384) WIH[idx] = Wih[idx];
    BIH[tid] = bih[tid]; BHH[tid] = bhh[tid];
    __syncthreads();

    const int s = tid >> 7, i = tid & 127;

    for (int tile = blockIdx.x; tile < (BB + 2) / 3; tile += gridDim.x) {
        const int seq0 = tile * 3;
        __syncthreads();
        if (tid < 48) {
            int sq = seq0 + tid / 16;
            X[tid] = (sq < BB) ? traj[sq * 16 + (tid & 15)] : 0.0f;
        }
        H[tid] = 0.0f;
        __syncthreads();

        for (int t = 0; t < 8; ++t) {
            {
                float b = BHH[tid];
                float a0 = b, a1 = b, a2 = b;
                #pragma unroll
                for (int k = 0; k < 128; k += 4) {
                    float4 h0 = *reinterpret_cast<const float4*>(H + k);
                    float4 h1 = *reinterpret_cast<const float4*>(H + 128 + k);
                    float4 h2 = *reinterpret_cast<const float4*>(H + 256 + k);
                    float w0 = WT[(k  )*385+tid], w1 = WT[(k+1)*385+tid];
                    float w2 = WT[(k+2)*385+tid], w3 = WT[(k+3)*385+tid];
                    a0 = fmaf(w0,h0.x,fmaf(w1,h0.y,fmaf(w2,h0.z,fmaf(w3,h0.w,a0))));
                    a1 = fmaf(w0,h1.x,fmaf(w1,h1.y,fmaf(w2,h1.z,fmaf(w3,h1.w,a1))));
                    a2 = fmaf(w0,h2.x,fmaf(w1,h2.y,fmaf(w2,h2.z,fmaf(w3,h2.w,a2))));
                }
                HP[tid] = a0; HP[384 + tid] = a1; HP[768 + tid] = a2;
            }
            __syncthreads();
            {
                float x0 = X[s*16 + t*2], x1 = X[s*16 + t*2 + 1];
                float xr = fmaf(x0, WIH[2*i],        fmaf(x1, WIH[2*i+1],        BIH[i]));
                float xz = fmaf(x0, WIH[2*(128+i)],  fmaf(x1, WIH[2*(128+i)+1],  BIH[128+i]));
                float xn = fmaf(x0, WIH[2*(256+i)],  fmaf(x1, WIH[2*(256+i)+1],  BIH[256+i]));
                float r = sigmoidf_(xr + HP[s*384 + i]);
                float z = sigmoidf_(xz + HP[s*384 + 128 + i]);
                float n = tanhf_(xn + r * HP[s*384 + 256 + i]);
                H[s*128 + i] = (1.0f - z) * n + z * H[s*128 + i];
            }
            __syncthreads();
        }
        int sq = seq0 + s;
        if (sq < BB) g_tf[sq * 128 + i] = H[s*128 + i];
    }
}

// =================== K3: sector features + per-sector MLP ===================
#define K3_W1T  0
#define K3_W2T  (K3_W1T + 68*129)
#define K3_NF   (K3_W2T + 128*129)
#define K3_FEAT (K3_NF + 4096)
#define K3_H1   (K3_FEAT + 8*68)
#define K3_WSUM (K3_H1 + 1024)
#define K3_WV   (K3_WSUM + 8)
#define K3_DIST (K3_WV + 64)
#define K3_VAL  (K3_DIST + 64)
#define K3_V0   (K3_VAL + 64)
#define K3_V1   (K3_V0 + 64)
#define K3_SMEM ((K3_V1 + 64) * 4)

__global__ __launch_bounds__(512)
void k3_sector(const float* __restrict__ ttraj, const float* __restrict__ ntraj,
               const float* __restrict__ ang, const float* __restrict__ mask,
               const float* __restrict__ W1, const float* __restrict__ b1,
               const float* __restrict__ W2, const float* __restrict__ b2)
{
    extern __shared__ float smf[];
    __shared__ int SID[64];
    float *W1T = smf + K3_W1T, *W2T = smf + K3_W2T, *NF = smf + K3_NF;
    float *FEAT = smf + K3_FEAT, *H1 = smf + K3_H1, *WSUM = smf + K3_WSUM;
    float *WV = smf + K3_WV, *DIST = smf + K3_DIST, *VAL = smf + K3_VAL;
    float *V0 = smf + K3_V0, *V1 = smf + K3_V1;
    const int tid = threadIdx.x;

    for (int idx = tid; idx < 128*68; idx += 512)
        W1T[(idx % 68) * 129 + (idx / 68)] = W1[idx];
    for (int idx = tid; idx < 128*128; idx += 512)
        W2T[(idx & 127) * 129 + (idx >> 7)] = W2[idx];
    __syncthreads();

    const int s = tid >> 6, i = tid & 63;

    for (int b = blockIdx.x; b < BB; b += gridDim.x) {
        __syncthreads();
        for (int idx = tid; idx < 4096; idx += 512)
            NF[idx] = g_nf[b * 4096 + idx];
        if (tid < 64) {
            const float* base = ntraj + (size_t)(b * 64 + tid) * 16;
            float px = base[14], py = base[15];
            float dx = px - ttraj[b*16 + 14], dy = py - ttraj[b*16 + 15];
            float d = sqrtf(dx*dx + dy*dy);
            DIST[tid] = d;
            V0[tid] = px - base[12];
            V1[tid] = py - base[13];
            int sid = (int)(ang[b*64 + tid] * 1.27323954473516f);
            SID[tid] = min(max(sid, 0), 7);
            float vf = (mask[b*64 + tid] > 0.0f) ? 1.0f : 0.0f;
            VAL[tid] = vf;
            WV[tid] = __expf(-d * 0.1f) * vf;
        }
        __syncthreads();
        if (tid < 8) {
            float cnt = 0.f, dsum = 0.f, v0 = 0.f, v1 = 0.f, ws = 0.f;
            for (int n = 0; n < 64; ++n) {
                bool in = (SID[n] == tid);
                float m = in ? VAL[n] : 0.0f;
                cnt += m; dsum += m * DIST[n]; v0 += m * V0[n]; v1 += m * V1[n];
                ws += in ? WV[n] : 0.0f;
            }
            float safe = fmaxf(cnt, 1.0f);
            bool ne = cnt > 0.0f;
            FEAT[tid*68 + 0] = cnt;
            FEAT[tid*68 + 1] = ne ? dsum / safe : 0.0f;
            FEAT[tid*68 + 2] = ne ? v0 / safe : 0.0f;
            FEAT[tid*68 + 3] = ne ? v1 / safe : 0.0f;
            WSUM[tid] = ws + 1e-8f;
        }
        __syncthreads();
        {
            float acc = 0.0f;
            for (int n = 0; n < 64; ++n) {
                float wm = (SID[n] == s) ? WV[n] : 0.0f;
                acc = fmaf(wm, NF[n*64 + i], acc);
            }
            FEAT[s*68 + 4 + i] = acc / WSUM[s];
        }
        __syncthreads();
        for (int o = tid; o < 1024; o += 512) {
            int os = o >> 7, oj = o & 127;
            float acc = b1[oj];
            #pragma unroll
            for (int k = 0; k < 68; ++k)
                acc = fmaf(FEAT[os*68 + k], W1T[k*129 + oj], acc);
            H1[os*128 + oj] = fmaxf(acc, 0.0f);
        }
        __syncthreads();
        for (int o = tid; o < 1024; o += 512) {
            int os = o >> 7, oj = o & 127;
            float acc = b2[oj];
            #pragma unroll
            for (int k = 0; k < 128; ++k)
                acc = fmaf(H1[os*128 + k], W2T[k*129 + oj], acc);
            g_enc[b * 1024 + o] = fmaxf(acc, 0.0f);
        }
    }
}

// =================== K5: f1 = relu([tf,enc] @ Wf1.T + bf1) ===================
// single shared buffer + register prefetch; smem 34.4KB -> ~6 blocks/SM
#define K5_PAD 12
#define K5_SMEM ((32*257 + 32*K5_PAD) * 4)

__global__ __launch_bounds__(256)
void k5_f1(const float* __restrict__ Wf1, const float* __restrict__ bf1)
{
    extern __shared__ float k5s[];
    float* Wsh = k5s;
    float* Ash = k5s + 32 * 257;

    const int tid = threadIdx.x;
    const int m0 = blockIdx.x * 8;
    const int jb = tid >> 5, kk = tid & 31;

    float acc[8];
    float bv = bf1[tid];
    #pragma unroll
    for (int r = 0; r < 8; ++r) acc[r] = bv;

    float wreg[32];
    float areg;

    #pragma unroll
    for (int rr = 0; rr < 32; ++rr)
        wreg[rr] = Wf1[(jb + rr * 8) * 1152 + kk];
    areg = g_tf[(m0 + jb) * 128 + kk];

    for (int c = 0; c < 36; ++c) {
        __syncthreads();
        #pragma unroll
        for (int rr = 0; rr < 32; ++rr)
            Wsh[kk * 257 + jb + rr * 8] = wreg[rr];
        Ash[kk * K5_PAD + jb] = areg;
        __syncthreads();
        if (c < 35) {
            const int k0 = (c + 1) * 32;
            #pragma unroll
            for (int rr = 0; rr < 32; ++rr)
                wreg[rr] = Wf1[(jb + rr * 8) * 1152 + k0 + kk];
            int gk = k0 + kk;
            areg = (gk < 128) ? g_tf[(m0 + jb) * 128 + gk]
                              : g_enc[(m0 + jb) * 1024 + gk - 128];
        }
        #pragma unroll
        for (int q = 0; q < 32; ++q) {
            float w = Wsh[q * 257 + tid];
            float4 a0 = *reinterpret_cast<const float4*>(&Ash[q * K5_PAD]);
            float4 a1 = *reinterpret_cast<const float4*>(&Ash[q * K5_PAD + 4]);
            acc[0]=fmaf(w,a0.x,acc[0]); acc[1]=fmaf(w,a0.y,acc[1]);
            acc[2]=fmaf(w,a0.z,acc[2]); acc[3]=fmaf(w,a0.w,acc[3]);
            acc[4]=fmaf(w,a1.x,acc[4]); acc[5]=fmaf(w,a1.y,acc[5]);
            acc[6]=fmaf(w,a1.z,acc[6]); acc[7]=fmaf(w,a1.w,acc[7]);
        }
    }
    #pragma unroll
    for (int r = 0; r < 8; ++r)
        g_f1[(m0 + r) * 256 + tid] = fmaxf(acc[r], 0.0f);
}

// =================== K6: f2, f3, LayerNorm ===================
#define K6_W2T 0
#define K6_W3T (K6_W2T + 256*129)
#define K6_F1  (K6_W3T + 128*65)
#define K6_F2  (K6_F1 + 16*257)
#define K6_F3  (K6_F2 + 16*129)
#define K6_MU  (K6_F3 + 1024)
#define K6_RS  (K6_MU + 16)
#define K6_SMEM ((K6_RS + 16) * 4)

__global__ __launch_bounds__(128)
void k6_final(const float* __restrict__ Wf2, const float* __restrict__ bf2,
              const float* __restrict__ Wf3, const float* __restrict__ bf3,
              const float* __restrict__ ln_g, const float* __restrict__ ln_b,
              float* __restrict__ out)
{
    extern __shared__ float smf[];
    float *W2T = smf + K6_W2T, *W3T = smf + K6_W3T, *F1 = smf + K6_F1;
    float *F2 = smf + K6_F2, *F3 = smf + K6_F3, *MU = smf + K6_MU, *RS = smf + K6_RS;
    const int tid = threadIdx.x;
    const int m0 = blockIdx.x * 16;

    for (int idx = tid; idx < 128*256; idx += 128)
        W2T[(idx & 255) * 129 + (idx >> 8)] = Wf2[idx];
    for (int idx = tid; idx < 64*128; idx += 128)
        W3T[(idx & 127) * 65 + (idx >> 7)] = Wf3[idx];
    for (int idx = tid; idx < 16*256; idx += 128)
        F1[(idx >> 8) * 257 + (idx & 255)] = g_f1[m0 * 256 + idx];
    __syncthreads();

    {
        float acc[16];
        float bv = bf2[tid];
        #pragma unroll
        for (int r = 0; r < 16; ++r) acc[r] = bv;
        for (int k = 0; k < 256; ++k) {
            float w = W2T[k * 129 + tid];
            #pragma unroll
            for (int r = 0; r < 16; ++r)
                acc[r] = fmaf(F1[r * 257 + k], w, acc[r]);
        }
        #pragma unroll
        for (int r = 0; r < 16; ++r)
            F2[r * 129 + tid] = fmaxf(acc[r], 0.0f);
    }
    __syncthreads();
    for (int o = tid; o < 1024; o += 128) {
        int r = o >> 6, j = o & 63;
        float acc = bf3[j];
        #pragma unroll
        for (int k = 0; k < 128; ++k)
            acc = fmaf(F2[r * 129 + k], W3T[k * 65 + j], acc);
        F3[o] = fmaxf(acc, 0.0f);
    }
    __syncthreads();
    if (tid < 16) {
        float s0 = 0.f;
        #pragma unroll
        for (int j = 0; j < 64; ++j) s0 += F3[tid*64 + j];
        float mu = s0 * (1.0f / 64.0f);
        float v = 0.f;
        #pragma unroll
        for (int j = 0; j < 64; ++j) { float d = F3[tid*64 + j] - mu; v = fmaf(d, d, v); }
        MU[tid] = mu;
        RS[tid] = rsqrtf(v * (1.0f / 64.0f) + 1e-5f);
    }
    __syncthreads();
    for (int o = tid; o < 1024; o += 128) {
        int r = o >> 6, j = o & 63;
        out[(m0 + r) * 64 + j] = (F3[o] - MU[r]) * RS[r] * ln_g[j] + ln_b[j];
    }
}

// =============================== launch ===============================
extern "C" void kernel_launch(void* const* d_in, const int* in_sizes, int n_in,
                              void* d_out, int out_size)
{
    const float* ttraj = (const float*)d_in[0];
    const float* ntraj = (const float*)d_in[1];
    const float* ang   = (const float*)d_in[2];
    const float* mask  = (const float*)d_in[3];
    const float* Wih_t = (const float*)d_in[4];
    const float* Whh_t = (const float*)d_in[5];
    const float* bih_t = (const float*)d_in[6];
    const float* bhh_t = (const float*)d_in[7];
    const float* Wih_n = (const float*)d_in[8];
    const float* Whh_n = (const float*)d_in[9];
    const float* bih_n = (const float*)d_in[10];
    const float* bhh_n = (const float*)d_in[11];
    const float* W1  = (const float*)d_in[12];
    const float* b1  = (const float*)d_in[13];
    const float* W2  = (const float*)d_in[14];
    const float* b2  = (const float*)d_in[15];
    const float* Wf1 = (const float*)d_in[16];
    const float* bf1 = (const float*)d_in[17];
    const float* Wf2 = (const float*)d_in[18];
    const float* bf2 = (const float*)d_in[19];
    const float* Wf3 = (const float*)d_in[20];
    const float* bf3 = (const float*)d_in[21];
    const float* ln_g = (const float*)d_in[22];
    const float* ln_b = (const float*)d_in[23];
    float* out = (float*)d_out;

    cudaFuncSetAttribute(k1_ngru,   cudaFuncAttributeMaxDynamicSharedMemorySize, G1_SMEM);
    cudaFuncSetAttribute(k2_tgru,   cudaFuncAttributeMaxDynamicSharedMemorySize, K2_SMEM);
    cudaFuncSetAttribute(k3_sector, cudaFuncAttributeMaxDynamicSharedMemorySize, K3_SMEM);
    cudaFuncSetAttribute(k5_f1,     cudaFuncAttributeMaxDynamicSharedMemorySize, K5_SMEM);
    cudaFuncSetAttribute(k6_final,  cudaFuncAttributeMaxDynamicSharedMemorySize, K6_SMEM);

    k1_ngru<<<296, 256, G1_SMEM>>>(ntraj, Wih_n, Whh_n, bih_n, bhh_n);
    k2_tgru<<<148, 384, K2_SMEM>>>(ttraj, Wih_t, Whh_t, bih_t, bhh_t);
    k3_sector<<<296, 512, K3_SMEM>>>(ttraj, ntraj, ang, mask, W1, b1, W2, b2);
    k5_f1<<<256, 256, K5_SMEM>>>(Wf1, bf1);
    k6_final<<<128, 128, K6_SMEM>>>(Wf2, bf2, Wf3, bf3, ln_g, ln_b, out);
}

// round 11
// speedup vs baseline: 2.4969x; 1.4725x over previous
#include <cuda_runtime.h>
#include <stdint.h>
#include <math.h>

#define BB   2048
#define NNB  64
#define HH   128
#define HN   64
#define NSEQ (BB*NNB)

__device__ float g_nf[NSEQ * HN];        // neighbor GRU features
__device__ float g_tf[BB * HH];          // target GRU features
__device__ float g_enc[BB * 8 * HH];     // per-sector MLP output
__device__ float g_f1[BB * 256];         // first final-MLP layer

__device__ __forceinline__ float sigmoidf_(float x) {
    return __fdividef(1.0f, 1.0f + __expf(-x));
}
__device__ __forceinline__ float tanhf_(float x) {
    return __fdividef(2.0f, 1.0f + __expf(-2.0f * x)) - 1.0f;
}
// pack two fp32 -> bf16x2 (lo in low half)
__device__ __forceinline__ uint32_t pack_bf2(float lo, float hi) {
    uint32_t r;
    asm("cvt.rn.bf16x2.f32 %0, %1, %2;" : "=r"(r) : "f"(hi), "f"(lo));
    return r;
}
__device__ __forceinline__ float bf_lo(uint32_t u) { return __uint_as_float(u << 16); }
__device__ __forceinline__ float bf_hi(uint32_t u) { return __uint_as_float(u & 0xFFFF0000u); }

__device__ __forceinline__ void mma16816(float* d, const uint32_t* a, uint2 b) {
    asm volatile("mma.sync.aligned.m16n8k16.row.col.f32.bf16.bf16.f32 "
        "{%0,%1,%2,%3}, {%4,%5,%6,%7}, {%8,%9}, {%0,%1,%2,%3};"
        : "+f"(d[0]), "+f"(d[1]), "+f"(d[2]), "+f"(d[3])
        : "r"(a[0]), "r"(a[1]), "r"(a[2]), "r"(a[3]), "r"(b.x), "r"(b.y));
}

// =============== K1: neighbor GRU via mma.sync bf16x3 (HMMA) ===============
// Warp tile = 16 seqs; block = 8 warps = 128 seqs; recurrence fully in regs.
// D(step t) fragments repack directly into A(step t+1) fragments.
#define H_WHI  0                 // u32[24][4][32][2]  24576 B  (Whh hi frags)
#define H_WLO  24576             // u32 same           24576 B  (Whh lo frags)
#define H_XS   49152             // float2[8][128]      8192 B
#define H_WIH  57344             // float2[192]         1536 B
#define H_BIH  58880             // float[192]           768 B
#define H_BHH  59648             // float[192]           768 B
#define H_SMEM 60416
#define H_NTILE (NSEQ / 128)     // 1024

__global__ __launch_bounds__(256, 1)
void k1_ngru(const float* __restrict__ traj, const float* __restrict__ Wih,
             const float* __restrict__ Whh, const float* __restrict__ bih,
             const float* __restrict__ bhh)
{
    extern __shared__ char sh[];
    uint32_t* WHI = (uint32_t*)(sh + H_WHI);
    uint32_t* WLO = (uint32_t*)(sh + H_WLO);
    float2*   XS2 = (float2*)(sh + H_XS);
    float2*   WIH2= (float2*)(sh + H_WIH);
    float*    BIH = (float*)(sh + H_BIH);
    float*    BHH = (float*)(sh + H_BHH);

    const int tid  = threadIdx.x;
    const int lane = tid & 31;
    const int w    = tid >> 5;
    const int g    = lane >> 2;     // row group 0..7
    const int tig  = lane & 3;      // thread in group

    // stage Whh fragments (hi/lo bf16 split), layout ((jt*4+kt)*32+lane)*2+r
    for (int e = tid; e < 3072; e += 256) {
        int l = e & 31, jtkt = e >> 5;
        int kt = jtkt & 3, jt = jtkt >> 2;
        int j = 8 * jt + (l >> 2);
        #pragma unroll
        for (int r = 0; r < 2; ++r) {
            int k = 16 * kt + 2 * (l & 3) + 8 * r;
            float w0 = Whh[j * 64 + k], w1 = Whh[j * 64 + k + 1];
            uint32_t hi = pack_bf2(w0, w1);
            uint32_t lo = pack_bf2(w0 - bf_lo(hi), w1 - bf_hi(hi));
            WHI[e * 2 + r] = hi;
            WLO[e * 2 + r] = lo;
        }
    }
    if (tid < 192) {
        WIH2[tid] = ((const float2*)Wih)[tid];
        BIH[tid] = bih[tid];
        BHH[tid] = bhh[tid];
    }
    __syncthreads();

    const int sl = w * 16 + g;      // lane's low seq within 128-tile

    for (int tile = blockIdx.x; tile < H_NTILE; tile += gridDim.x) {
        __syncthreads();            // protect XS from previous-tile readers
        {   // stage x: XS2[t][seq] = (x0,x1)
            int s_ = tid >> 1, q0 = (tid & 1) * 2;
            const float4* tp = (const float4*)(traj + (size_t)(tile * 128 + s_) * 16);
            float4 v0 = tp[q0], v1 = tp[q0 + 1];
            XS2[(2 * q0 + 0) * 128 + s_] = make_float2(v0.x, v0.y);
            XS2[(2 * q0 + 1) * 128 + s_] = make_float2(v0.z, v0.w);
            XS2[(2 * q0 + 2) * 128 + s_] = make_float2(v1.x, v1.y);
            XS2[(2 * q0 + 3) * 128 + s_] = make_float2(v1.z, v1.w);
        }
        __syncthreads();

        uint32_t Ahi[4][4], Alo[4][4];
        #pragma unroll
        for (int kt = 0; kt < 4; ++kt)
            #pragma unroll
            for (int r = 0; r < 4; ++r) { Ahi[kt][r] = 0u; Alo[kt][r] = 0u; }
        float d[24][4];

        for (int t = 0; t < 8; ++t) {
            // init D with bhh (accumulator carries the recurrent bias)
            #pragma unroll
            for (int jt = 0; jt < 24; ++jt) {
                float2 b2 = *(const float2*)&BHH[8 * jt + 2 * tig];
                d[jt][0] = b2.x; d[jt][1] = b2.y; d[jt][2] = b2.x; d[jt][3] = b2.y;
            }
            if (t > 0) {
                #pragma unroll
                for (int jt = 0; jt < 24; ++jt) {
                    uint2 bh[4], bl[4];
                    #pragma unroll
                    for (int kt = 0; kt < 4; ++kt) {
                        bh[kt] = *(const uint2*)&WHI[((jt * 4 + kt) * 32 + lane) * 2];
                        bl[kt] = *(const uint2*)&WLO[((jt * 4 + kt) * 32 + lane) * 2];
                    }
                    #pragma unroll
                    for (int kt = 0; kt < 4; ++kt) mma16816(d[jt], Ahi[kt], bh[kt]);
                    #pragma unroll
                    for (int kt = 0; kt < 4; ++kt) mma16816(d[jt], Ahi[kt], bl[kt]);
                    #pragma unroll
                    for (int kt = 0; kt < 4; ++kt) mma16816(d[jt], Alo[kt], bh[kt]);
                }
            }
            // gates (fragment-local: r/z/n for col i live in tiles jt, jt+8, jt+16)
            float2 xA = XS2[t * 128 + sl];
            float2 xB = XS2[t * 128 + sl + 8];
            #pragma unroll
            for (int jt = 0; jt < 8; ++jt) {
                float4 wr4 = *(const float4*)&WIH2[8 * jt + 2 * tig];
                float4 wz4 = *(const float4*)&WIH2[64 + 8 * jt + 2 * tig];
                float4 wn4 = *(const float4*)&WIH2[128 + 8 * jt + 2 * tig];
                float2 br2 = *(const float2*)&BIH[8 * jt + 2 * tig];
                float2 bz2 = *(const float2*)&BIH[64 + 8 * jt + 2 * tig];
                float2 bn2 = *(const float2*)&BIH[128 + 8 * jt + 2 * tig];
                const int kt = jt >> 1;
                #pragma unroll
                for (int rh = 0; rh < 2; ++rh) {
                    float x0 = rh ? xB.x : xA.x;
                    float x1 = rh ? xB.y : xA.y;
                    const int reg = (jt & 1) * 2 + rh;
                    uint32_t uh = Ahi[kt][reg], ul = Alo[kt][reg];
                    float hold0 = bf_lo(uh) + bf_lo(ul);
                    float hold1 = bf_hi(uh) + bf_hi(ul);
                    float hnew0, hnew1;
                    #pragma unroll
                    for (int c = 0; c < 2; ++c) {
                        float hr = d[jt][rh * 2 + c];
                        float hz = d[jt + 8][rh * 2 + c];
                        float hn = d[jt + 16][rh * 2 + c];
                        float wrx = c ? wr4.z : wr4.x, wry = c ? wr4.w : wr4.y;
                        float wzx = c ? wz4.z : wz4.x, wzy = c ? wz4.w : wz4.y;
                        float wnx = c ? wn4.z : wn4.x, wny = c ? wn4.w : wn4.y;
                        float xr = fmaf(x0, wrx, fmaf(x1, wry, c ? br2.y : br2.x));
                        float xz = fmaf(x0, wzx, fmaf(x1, wzy, c ? bz2.y : bz2.x));
                        float xn = fmaf(x0, wnx, fmaf(x1, wny, c ? bn2.y : bn2.x));
                        float r = sigmoidf_(xr + hr);
                        float z = sigmoidf_(xz + hz);
                        float n = tanhf_(fmaf(r, hn, xn));
                        float hold = c ? hold1 : hold0;
                        float h = fmaf(z, hold - n, n);
                        if (c) hnew1 = h; else hnew0 = h;
                    }
                    if (t < 7) {
                        uint32_t nh = pack_bf2(hnew0, hnew1);
                        uint32_t nl = pack_bf2(hnew0 - bf_lo(nh), hnew1 - bf_hi(nh));
                        Ahi[kt][reg] = nh; Alo[kt][reg] = nl;
                    } else {
                        int seq = tile * 128 + sl + 8 * rh;
                        *(float2*)&g_nf[(size_t)seq * 64 + 8 * jt + 2 * tig] =
                            make_float2(hnew0, hnew1);
                    }
                }
            }
        }
    }
}

// ============================ K2: target GRU ============================
#define K2_WT  0
#define K2_HP  (K2_WT + 128*385)
#define K2_H   (K2_HP + 3*384)
#define K2_X   (K2_H + 384)
#define K2_WIH (K2_X + 48)
#define K2_BIH (K2_WIH + 768)
#define K2_BHH (K2_BIH + 384)
#define K2_SMEM ((K2_BHH + 384) * 4)

__global__ __launch_bounds__(384)
void k2_tgru(const float* __restrict__ traj, const float* __restrict__ Wih,
             const float* __restrict__ Whh, const float* __restrict__ bih,
             const float* __restrict__ bhh)
{
    extern __shared__ float sm[];
    float *WT = sm + K2_WT, *HP = sm + K2_HP, *H = sm + K2_H, *X = sm + K2_X;
    float *WIH = sm + K2_WIH, *BIH = sm + K2_BIH, *BHH = sm + K2_BHH;
    const int tid = threadIdx.x;

    for (int idx = tid; idx < 384*128; idx += 384)
        WT[(idx & 127) * 385 + (idx >> 7)] = Whh[idx];
    for (int idx = tid; idx < 768; idx += 384) WIH[idx] = Wih[idx];
    BIH[tid] = bih[tid]; BHH[tid] = bhh[tid];
    __syncthreads();

    const int s = tid >> 7, i = tid & 127;

    for (int tile = blockIdx.x; tile < (BB + 2) / 3; tile += gridDim.x) {
        const int seq0 = tile * 3;
        __syncthreads();
        if (tid < 48) {
            int sq = seq0 + tid / 16;
            X[tid] = (sq < BB) ? traj[sq * 16 + (tid & 15)] : 0.0f;
        }
        H[tid] = 0.0f;
        __syncthreads();

        for (int t = 0; t < 8; ++t) {
            {
                float b = BHH[tid];
                float a0 = b, a1 = b, a2 = b;
                #pragma unroll
                for (int k = 0; k < 128; k += 4) {
                    float4 h0 = *reinterpret_cast<const float4*>(H + k);
                    float4 h1 = *reinterpret_cast<const float4*>(H + 128 + k);
                    float4 h2 = *reinterpret_cast<const float4*>(H + 256 + k);
                    float w0 = WT[(k  )*385+tid], w1 = WT[(k+1)*385+tid];
                    float w2 = WT[(k+2)*385+tid], w3 = WT[(k+3)*385+tid];
                    a0 = fmaf(w0,h0.x,fmaf(w1,h0.y,fmaf(w2,h0.z,fmaf(w3,h0.w,a0))));
                    a1 = fmaf(w0,h1.x,fmaf(w1,h1.y,fmaf(w2,h1.z,fmaf(w3,h1.w,a1))));
                    a2 = fmaf(w0,h2.x,fmaf(w1,h2.y,fmaf(w2,h2.z,fmaf(w3,h2.w,a2))));
                }
                HP[tid] = a0; HP[384 + tid] = a1; HP[768 + tid] = a2;
            }
            __syncthreads();
            {
                float x0 = X[s*16 + t*2], x1 = X[s*16 + t*2 + 1];
                float xr = fmaf(x0, WIH[2*i],        fmaf(x1, WIH[2*i+1],        BIH[i]));
                float xz = fmaf(x0, WIH[2*(128+i)],  fmaf(x1, WIH[2*(128+i)+1],  BIH[128+i]));
                float xn = fmaf(x0, WIH[2*(256+i)],  fmaf(x1, WIH[2*(256+i)+1],  BIH[256+i]));
                float r = sigmoidf_(xr + HP[s*384 + i]);
                float z = sigmoidf_(xz + HP[s*384 + 128 + i]);
                float n = tanhf_(xn + r * HP[s*384 + 256 + i]);
                H[s*128 + i] = (1.0f - z) * n + z * H[s*128 + i];
            }
            __syncthreads();
        }
        int sq = seq0 + s;
        if (sq < BB) g_tf[sq * 128 + i] = H[s*128 + i];
    }
}

// =================== K3: sector features + per-sector MLP ===================
#define K3_W1T  0
#define K3_W2T  (K3_W1T + 68*129)
#define K3_NF   (K3_W2T + 128*129)
#define K3_FEAT (K3_NF + 4096)
#define K3_H1   (K3_FEAT + 8*68)
#define K3_WSUM (K3_H1 + 1024)
#define K3_WV   (K3_WSUM + 8)
#define K3_DIST (K3_WV + 64)
#define K3_VAL  (K3_DIST + 64)
#define K3_V0   (K3_VAL + 64)
#define K3_V1   (K3_V0 + 64)
#define K3_SMEM ((K3_V1 + 64) * 4)

__global__ __launch_bounds__(512)
void k3_sector(const float* __restrict__ ttraj, const float* __restrict__ ntraj,
               const float* __restrict__ ang, const float* __restrict__ mask,
               const float* __restrict__ W1, const float* __restrict__ b1,
               const float* __restrict__ W2, const float* __restrict__ b2)
{
    extern __shared__ float smf[];
    __shared__ int SID[64];
    float *W1T = smf + K3_W1T, *W2T = smf + K3_W2T, *NF = smf + K3_NF;
    float *FEAT = smf + K3_FEAT, *H1 = smf + K3_H1, *WSUM = smf + K3_WSUM;
    float *WV = smf + K3_WV, *DIST = smf + K3_DIST, *VAL = smf + K3_VAL;
    float *V0 = smf + K3_V0, *V1 = smf + K3_V1;
    const int tid = threadIdx.x;

    for (int idx = tid; idx < 128*68; idx += 512)
        W1T[(idx % 68) * 129 + (idx / 68)] = W1[idx];
    for (int idx = tid; idx < 128*128; idx += 512)
        W2T[(idx & 127) * 129 + (idx >> 7)] = W2[idx];
    __syncthreads();

    const int s = tid >> 6, i = tid & 63;

    for (int b = blockIdx.x; b < BB; b += gridDim.x) {
        __syncthreads();
        for (int idx = tid; idx < 4096; idx += 512)
            NF[idx] = g_nf[b * 4096 + idx];
        if (tid < 64) {
            const float* base = ntraj + (size_t)(b * 64 + tid) * 16;
            float px = base[14], py = base[15];
            float dx = px - ttraj[b*16 + 14], dy = py - ttraj[b*16 + 15];
            float d = sqrtf(dx*dx + dy*dy);
            DIST[tid] = d;
            V0[tid] = px - base[12];
            V1[tid] = py - base[13];
            int sid = (int)(ang[b*64 + tid] * 1.27323954473516f);
            SID[tid] = min(max(sid, 0), 7);
            float vf = (mask[b*64 + tid] > 0.0f) ? 1.0f : 0.0f;
            VAL[tid] = vf;
            WV[tid] = __expf(-d * 0.1f) * vf;
        }
        __syncthreads();
        if (tid < 8) {
            float cnt = 0.f, dsum = 0.f, v0 = 0.f, v1 = 0.f, ws = 0.f;
            for (int n = 0; n < 64; ++n) {
                bool in = (SID[n] == tid);
                float m = in ? VAL[n] : 0.0f;
                cnt += m; dsum += m * DIST[n]; v0 += m * V0[n]; v1 += m * V1[n];
                ws += in ? WV[n] : 0.0f;
            }
            float safe = fmaxf(cnt, 1.0f);
            bool ne = cnt > 0.0f;
            FEAT[tid*68 + 0] = cnt;
            FEAT[tid*68 + 1] = ne ? dsum / safe : 0.0f;
            FEAT[tid*68 + 2] = ne ? v0 / safe : 0.0f;
            FEAT[tid*68 + 3] = ne ? v1 / safe : 0.0f;
            WSUM[tid] = ws + 1e-8f;
        }
        __syncthreads();
        {
            float acc = 0.0f;
            for (int n = 0; n < 64; ++n) {
                float wm = (SID[n] == s) ? WV[n] : 0.0f;
                acc = fmaf(wm, NF[n*64 + i], acc);
            }
            FEAT[s*68 + 4 + i] = acc / WSUM[s];
        }
        __syncthreads();
        for (int o = tid; o < 1024; o += 512) {
            int os = o >> 7, oj = o & 127;
            float acc = b1[oj];
            #pragma unroll
            for (int k = 0; k < 68; ++k)
                acc = fmaf(FEAT[os*68 + k], W1T[k*129 + oj], acc);
            H1[os*128 + oj] = fmaxf(acc, 0.0f);
        }
        __syncthreads();
        for (int o = tid; o < 1024; o += 512) {
            int os = o >> 7, oj = o & 127;
            float acc = b2[oj];
            #pragma unroll
            for (int k = 0; k < 128; ++k)
                acc = fmaf(H1[os*128 + k], W2T[k*129 + oj], acc);
            g_enc[b * 1024 + o] = fmaxf(acc, 0.0f);
        }
    }
}

// =================== K5: f1 = relu([tf,enc] @ Wf1.T + bf1) ===================
#define K5_PAD 12
#define K5_SMEM ((32*257 + 32*K5_PAD) * 4)

__global__ __launch_bounds__(256)
void k5_f1(const float* __restrict__ Wf1, const float* __restrict__ bf1)
{
    extern __shared__ float k5s[];
    float* Wsh = k5s;
    float* Ash = k5s + 32 * 257;

    const int tid = threadIdx.x;
    const int m0 = blockIdx.x * 8;
    const int jb = tid >> 5, kk = tid & 31;

    float acc[8];
    float bv = bf1[tid];
    #pragma unroll
    for (int r = 0; r < 8; ++r) acc[r] = bv;

    float wreg[32];
    float areg;

    #pragma unroll
    for (int rr = 0; rr < 32; ++rr)
        wreg[rr] = Wf1[(jb + rr * 8) * 1152 + kk];
    areg = g_tf[(m0 + jb) * 128 + kk];

    for (int c = 0; c < 36; ++c) {
        __syncthreads();
        #pragma unroll
        for (int rr = 0; rr < 32; ++rr)
            Wsh[kk * 257 + jb + rr * 8] = wreg[rr];
        Ash[kk * K5_PAD + jb] = areg;
        __syncthreads();
        if (c < 35) {
            const int k0 = (c + 1) * 32;
            #pragma unroll
            for (int rr = 0; rr < 32; ++rr)
                wreg[rr] = Wf1[(jb + rr * 8) * 1152 + k0 + kk];
            int gk = k0 + kk;
            areg = (gk < 128) ? g_tf[(m0 + jb) * 128 + gk]
                              : g_enc[(m0 + jb) * 1024 + gk - 128];
        }
        #pragma unroll
        for (int q = 0; q < 32; ++q) {
            float w = Wsh[q * 257 + tid];
            float4 a0 = *reinterpret_cast<const float4*>(&Ash[q * K5_PAD]);
            float4 a1 = *reinterpret_cast<const float4*>(&Ash[q * K5_PAD + 4]);
            acc[0]=fmaf(w,a0.x,acc[0]); acc[1]=fmaf(w,a0.y,acc[1]);
            acc[2]=fmaf(w,a0.z,acc[2]); acc[3]=fmaf(w,a0.w,acc[3]);
            acc[4]=fmaf(w,a1.x,acc[4]); acc[5]=fmaf(w,a1.y,acc[5]);
            acc[6]=fmaf(w,a1.z,acc[6]); acc[7]=fmaf(w,a1.w,acc[7]);
        }
    }
    #pragma unroll
    for (int r = 0; r < 8; ++r)
        g_f1[(m0 + r) * 256 + tid] = fmaxf(acc[r], 0.0f);
}

// =================== K6: f2, f3, LayerNorm ===================
#define K6_W2T 0
#define K6_W3T (K6_W2T + 256*129)
#define K6_F1  (K6_W3T + 128*65)
#define K6_F2  (K6_F1 + 16*257)
#define K6_F3  (K6_F2 + 16*129)
#define K6_MU  (K6_F3 + 1024)
#define K6_RS  (K6_MU + 16)
#define K6_SMEM ((K6_RS + 16) * 4)

__global__ __launch_bounds__(128)
void k6_final(const float* __restrict__ Wf2, const float* __restrict__ bf2,
              const float* __restrict__ Wf3, const float* __restrict__ bf3,
              const float* __restrict__ ln_g, const float* __restrict__ ln_b,
              float* __restrict__ out)
{
    extern __shared__ float smf[];
    float *W2T = smf + K6_W2T, *W3T = smf + K6_W3T, *F1 = smf + K6_F1;
    float *F2 = smf + K6_F2, *F3 = smf + K6_F3, *MU = smf + K6_MU, *RS = smf + K6_RS;
    const int tid = threadIdx.x;
    const int m0 = blockIdx.x * 16;

    for (int idx = tid; idx < 128*256; idx += 128)
        W2T[(idx & 255) * 129 + (idx >> 8)] = Wf2[idx];
    for (int idx = tid; idx < 64*128; idx += 128)
        W3T[(idx & 127) * 65 + (idx >> 7)] = Wf3[idx];
    for (int idx = tid; idx < 16*256; idx += 128)
        F1[(idx >> 8) * 257 + (idx & 255)] = g_f1[m0 * 256 + idx];
    __syncthreads();

    {
        float acc[16];
        float bv = bf2[tid];
        #pragma unroll
        for (int r = 0; r < 16; ++r) acc[r] = bv;
        for (int k = 0; k < 256; ++k) {
            float w = W2T[k * 129 + tid];
            #pragma unroll
            for (int r = 0; r < 16; ++r)
                acc[r] = fmaf(F1[r * 257 + k], w, acc[r]);
        }
        #pragma unroll
        for (int r = 0; r < 16; ++r)
            F2[r * 129 + tid] = fmaxf(acc[r], 0.0f);
    }
    __syncthreads();
    for (int o = tid; o < 1024; o += 128) {
        int r = o >> 6, j = o & 63;
        float acc = bf3[j];
        #pragma unroll
        for (int k = 0; k < 128; ++k)
            acc = fmaf(F2[r * 129 + k], W3T[k * 65 + j], acc);
        F3[o] = fmaxf(acc, 0.0f);
    }
    __syncthreads();
    if (tid < 16) {
        float s0 = 0.f;
        #pragma unroll
        for (int j = 0; j < 64; ++j) s0 += F3[tid*64 + j];
        float mu = s0 * (1.0f / 64.0f);
        float v = 0.f;
        #pragma unroll
        for (int j = 0; j < 64; ++j) { float dd = F3[tid*64 + j] - mu; v = fmaf(dd, dd, v); }
        MU[tid] = mu;
        RS[tid] = rsqrtf(v * (1.0f / 64.0f) + 1e-5f);
    }
    __syncthreads();
    for (int o = tid; o < 1024; o += 128) {
        int r = o >> 6, j = o & 63;
        out[(m0 + r) * 64 + j] = (F3[o] - MU[r]) * RS[r] * ln_g[j] + ln_b[j];
    }
}

// =============================== launch ===============================
extern "C" void kernel_launch(void* const* d_in, const int* in_sizes, int n_in,
                              void* d_out, int out_size)
{
    const float* ttraj = (const float*)d_in[0];
    const float* ntraj = (const float*)d_in[1];
    const float* ang   = (const float*)d_in[2];
    const float* mask  = (const float*)d_in[3];
    const float* Wih_t = (const float*)d_in[4];
    const float* Whh_t = (const float*)d_in[5];
    const float* bih_t = (const float*)d_in[6];
    const float* bhh_t = (const float*)d_in[7];
    const float* Wih_n = (const float*)d_in[8];
    const float* Whh_n = (const float*)d_in[9];
    const float* bih_n = (const float*)d_in[10];
    const float* bhh_n = (const float*)d_in[11];
    const float* W1  = (const float*)d_in[12];
    const float* b1  = (const float*)d_in[13];
    const float* W2  = (const float*)d_in[14];
    const float* b2  = (const float*)d_in[15];
    const float* Wf1 = (const float*)d_in[16];
    const float* bf1 = (const float*)d_in[17];
    const float* Wf2 = (const float*)d_in[18];
    const float* bf2 = (const float*)d_in[19];
    const float* Wf3 = (const float*)d_in[20];
    const float* bf3 = (const float*)d_in[21];
    const float* ln_g = (const float*)d_in[22];
    const float* ln_b = (const float*)d_in[23];
    float* out = (float*)d_out;

    cudaFuncSetAttribute(k1_ngru,   cudaFuncAttributeMaxDynamicSharedMemorySize, H_SMEM);
    cudaFuncSetAttribute(k2_tgru,   cudaFuncAttributeMaxDynamicSharedMemorySize, K2_SMEM);
    cudaFuncSetAttribute(k3_sector, cudaFuncAttributeMaxDynamicSharedMemorySize, K3_SMEM);
    cudaFuncSetAttribute(k5_f1,     cudaFuncAttributeMaxDynamicSharedMemorySize, K5_SMEM);
    cudaFuncSetAttribute(k6_final,  cudaFuncAttributeMaxDynamicSharedMemorySize, K6_SMEM);

    k1_ngru<<<148, 256, H_SMEM>>>(ntraj, Wih_n, Whh_n, bih_n, bhh_n);
    k2_tgru<<<148, 384, K2_SMEM>>>(ttraj, Wih_t, Whh_t, bih_t, bhh_t);
    k3_sector<<<296, 512, K3_SMEM>>>(ttraj, ntraj, ang, mask, W1, b1, W2, b2);
    k5_f1<<<256, 256, K5_SMEM>>>(Wf1, bf1);
    k6_final<<<128, 128, K6_SMEM>>>(Wf2, bf2, Wf3, bf3, ln_g, ln_b, out);
}